// round 1
// baseline (speedup 1.0000x reference)
#include <cuda_runtime.h>
#include <math.h>

#define BSZ   8192
#define MDIM  128
#define NDIM  128
#define KDIM  256
#define MN    16384

// -------- device scratch (no allocations allowed) --------
__device__ float g_wsq[MN];
__device__ float g_xsq[BSZ];
__device__ int   g_bmu[BSZ];
__device__ float g_px[BSZ * MDIM];
__device__ float g_py[BSZ * NDIM];
__device__ float g_denom[MN];
__device__ float g_sched[2];   // [0] = d = 2*sigma^2, [1] = lr

// ============================================================
// Kernel 1: row sums of squares for W (16384 rows) and X (8192 rows),
// plus the scalar schedule (sigma/lr) computed from `it`.
// One warp per row.
// ============================================================
__global__ void ker_sq(const float* __restrict__ W,
                       const float* __restrict__ X,
                       const int*  __restrict__ itp) {
    if (blockIdx.x == 0 && threadIdx.x == 0) {
        int it = itp[0];
        double TAU   = 20.0 / log(64.0);
        double sigma = 64.0 * exp(-(double)it / TAU);
        g_sched[0] = (float)(2.0 * sigma * sigma);
        g_sched[1] = (float)(0.5 * exp(-(double)it / 20.0));
    }
    int warp = (blockIdx.x * blockDim.x + threadIdx.x) >> 5;
    int lane = threadIdx.x & 31;
    const float* src;
    float* dst;
    if (warp < MN) {
        src = W + (size_t)warp * KDIM;
        dst = g_wsq + warp;
    } else if (warp < MN + BSZ) {
        int row = warp - MN;
        src = X + (size_t)row * KDIM;
        dst = g_xsq + row;
    } else {
        return;
    }
    float s = 0.f;
#pragma unroll
    for (int c = lane; c < KDIM; c += 32) {
        float v = src[c];
        s += v * v;
    }
#pragma unroll
    for (int o = 16; o > 0; o >>= 1) s += __shfl_down_sync(0xffffffffu, s, o);
    if (lane == 0) *dst = s;
}

// ============================================================
// Kernel 2: fused distance GEMM + argmin.
// Each CTA handles 64 data rows (b) against all 16384 units (j).
// X tile [64 x 256] persistent in SMEM (transposed [k][b]);
// W tiles [128 j x 64 k] streamed.
// Thread micro-tile: 4 b (tx, float4 from Xs) x 8 j (ty, broadcast from Ws).
// score = sqrt((x^2 + w^2) - 2*dot) replicating the reference expression,
// first-occurrence tie break like argmin.
// dyn smem: Xs[256][68] + Ws[128][68] = 104448 B
// ============================================================
__global__ void __launch_bounds__(256, 1)
ker_dist(const float* __restrict__ X, const float* __restrict__ W) {
    extern __shared__ float sm[];
    float* Xs = sm;              // [256][68]  (k-major, b fast)
    float* Ws = sm + 256 * 68;   // [128][68]  (j-major, k fast)

    const int tid = threadIdx.x;
    const int tx  = tid & 15;    // -> b group
    const int ty  = tid >> 4;    // -> j group
    const int b0  = blockIdx.x * 64;

    // Load X tile once, transposed: Xs[k][b]. Lanes vary b (conflict-free stores).
    for (int i = tid; i < 64 * 64; i += 256) {
        int b  = i & 63;
        int kq = i >> 6;
        float4 v = *(const float4*)(X + (size_t)(b0 + b) * KDIM + kq * 4);
        Xs[(kq * 4 + 0) * 68 + b] = v.x;
        Xs[(kq * 4 + 1) * 68 + b] = v.y;
        Xs[(kq * 4 + 2) * 68 + b] = v.z;
        Xs[(kq * 4 + 3) * 68 + b] = v.w;
    }

    float xsq[4];
#pragma unroll
    for (int r = 0; r < 4; r++) xsq[r] = g_xsq[b0 + tx * 4 + r];

    float bestv[4];
    int   bestj[4];
#pragma unroll
    for (int r = 0; r < 4; r++) { bestv[r] = 3.4e38f; bestj[r] = 0; }

    for (int jt = 0; jt < 128; ++jt) {
        const int j0 = jt * 128;
        float acc[4][8];
#pragma unroll
        for (int r = 0; r < 4; r++)
#pragma unroll
            for (int c = 0; c < 8; c++) acc[r][c] = 0.f;

        for (int kc = 0; kc < 4; ++kc) {
            __syncthreads();
            // Load W tile: Ws[j][k'] for k' in [0,64)
            for (int i = tid; i < 128 * 16; i += 256) {
                int j  = i >> 4;
                int kq = i & 15;
                float4 v = *(const float4*)(W + (size_t)(j0 + j) * KDIM + kc * 64 + kq * 4);
                *(float4*)&Ws[j * 68 + kq * 4] = v;
            }
            __syncthreads();

#pragma unroll
            for (int k4 = 0; k4 < 64; k4 += 4) {
                const int kg = kc * 64 + k4;
                float4 xa = *(const float4*)&Xs[(kg + 0) * 68 + tx * 4];
                float4 xb = *(const float4*)&Xs[(kg + 1) * 68 + tx * 4];
                float4 xc = *(const float4*)&Xs[(kg + 2) * 68 + tx * 4];
                float4 xd = *(const float4*)&Xs[(kg + 3) * 68 + tx * 4];
#pragma unroll
                for (int c = 0; c < 8; c++) {
                    float4 wv = *(const float4*)&Ws[(ty * 8 + c) * 68 + k4];
                    acc[0][c] += xa.x * wv.x + xb.x * wv.y + xc.x * wv.z + xd.x * wv.w;
                    acc[1][c] += xa.y * wv.x + xb.y * wv.y + xc.y * wv.z + xd.y * wv.w;
                    acc[2][c] += xa.z * wv.x + xb.z * wv.y + xc.z * wv.z + xd.z * wv.w;
                    acc[3][c] += xa.w * wv.x + xb.w * wv.y + xc.w * wv.z + xd.w * wv.w;
                }
            }
        }

        // epilogue: score + running argmin (j ascending per thread -> first-occurrence ties)
#pragma unroll
        for (int c = 0; c < 8; c++) {
            int j = j0 + ty * 8 + c;
            float w2 = g_wsq[j];
#pragma unroll
            for (int r = 0; r < 4; r++) {
                float s = sqrtf((xsq[r] + w2) - 2.0f * acc[r][c]);
                if (s < bestv[r]) { bestv[r] = s; bestj[r] = j; }
            }
        }
    }

    // cross-thread (ty) reduction via SMEM scratch (reuse Ws region)
    __syncthreads();
    float* sv = Ws;                 // 64*16 floats
    int*   si = (int*)(Ws + 64 * 16);
#pragma unroll
    for (int r = 0; r < 4; r++) {
        int b = tx * 4 + r;
        sv[b * 16 + ty] = bestv[r];
        si[b * 16 + ty] = bestj[r];
    }
    __syncthreads();
    if (tid < 64) {
        float bv = 3.4e38f;
        int   bj = MN;
        for (int t = 0; t < 16; t++) {
            float v = sv[tid * 16 + t];
            int  jj = si[tid * 16 + t];
            if (v < bv || (v == bv && jj < bj)) { bv = v; bj = jj; }
        }
        g_bmu[b0 + tid] = bj;
    }
}

// ============================================================
// Kernel 3: px[b,m] = exp(-(m-win0)^2/d), py[b,n] = lr*exp(-(n-win1)^2/d)
// ============================================================
__global__ void ker_pxpy() {
    int b = blockIdx.x;
    int i = threadIdx.x;
    int bmu = g_bmu[b];
    float w0 = (float)(bmu >> 7);
    float w1 = (float)(bmu & 127);
    float d  = g_sched[0];
    float lr = g_sched[1];
    float fi = (float)i;
    float dr = fi - w0;
    float dc = fi - w1;
    g_px[b * 128 + i] = expf(-(dr * dr) / d);
    g_py[b * 128 + i] = lr * expf(-(dc * dc) / d);
}

// ============================================================
// Kernel 4: denom[m,n] = sum_b px[b,m]*py[b,n]
// ============================================================
__global__ void ker_denom() {
    int m = blockIdx.x;
    int n = threadIdx.x;
    float s = 0.f;
    for (int b = 0; b < BSZ; b += 8) {
#pragma unroll
        for (int u = 0; u < 8; u++)
            s += __ldg(&g_px[(b + u) * 128 + m]) * __ldg(&g_py[(b + u) * 128 + n]);
    }
    g_denom[m * 128 + n] = s;
}

// ============================================================
// Kernel 5: numer GEMM + divide.
// Per CTA: one m (blockIdx.y), one d-half (blockIdx.x). Output 128n x 128d.
// A[k][n] = px[b,m]*py[b,n] built on the fly; B[k][d] = X.  K = 8192 over b.
// Thread micro-tile 8n (ty) x 8d (tx).
// ============================================================
__global__ void __launch_bounds__(256)
ker_numer(const float* __restrict__ X, const float* __restrict__ Wold,
          float* __restrict__ OUT) {
    __shared__ float As[32 * 132];
    __shared__ float Bs[32 * 132];

    const int tid = threadIdx.x;
    const int tx  = tid & 15;     // -> d
    const int ty  = tid >> 4;     // -> n
    const int m   = blockIdx.y;
    const int d0  = blockIdx.x * 128;

    float acc[8][8];
#pragma unroll
    for (int i = 0; i < 8; i++)
#pragma unroll
        for (int jj = 0; jj < 8; jj++) acc[i][jj] = 0.f;

    for (int b0 = 0; b0 < BSZ; b0 += 32) {
        __syncthreads();
        for (int i = tid; i < 32 * 32; i += 256) {
            int k = i >> 5;
            int q = i & 31;
            float pxv = __ldg(&g_px[(b0 + k) * 128 + m]);
            float4 pv = *(const float4*)(g_py + (b0 + k) * 128 + q * 4);
            float4 av;
            av.x = pxv * pv.x; av.y = pxv * pv.y; av.z = pxv * pv.z; av.w = pxv * pv.w;
            *(float4*)&As[k * 132 + q * 4] = av;
            float4 xv = *(const float4*)(X + (size_t)(b0 + k) * KDIM + d0 + q * 4);
            *(float4*)&Bs[k * 132 + q * 4] = xv;
        }
        __syncthreads();

#pragma unroll 4
        for (int k = 0; k < 32; k++) {
            float4 bv0 = *(const float4*)&Bs[k * 132 + tx * 8];
            float4 bv1 = *(const float4*)&Bs[k * 132 + tx * 8 + 4];
            float4 a0  = *(const float4*)&As[k * 132 + ty * 8];
            float4 a1  = *(const float4*)&As[k * 132 + ty * 8 + 4];
            float a[8] = {a0.x, a0.y, a0.z, a0.w, a1.x, a1.y, a1.z, a1.w};
            float bb[8] = {bv0.x, bv0.y, bv0.z, bv0.w, bv1.x, bv1.y, bv1.z, bv1.w};
#pragma unroll
            for (int nn = 0; nn < 8; nn++)
#pragma unroll
                for (int dd = 0; dd < 8; dd++) acc[nn][dd] += a[nn] * bb[dd];
        }
    }

    // epilogue: out = numer/denom (denom > 0 always; keep where() for fidelity)
#pragma unroll
    for (int cn = 0; cn < 8; cn++) {
        int n = ty * 8 + cn;
        float den = g_denom[m * 128 + n];
        size_t base = ((size_t)(m * 128 + n)) * KDIM + d0 + tx * 8;
        if (den != 0.f) {
            float4 o0, o1;
            o0.x = acc[cn][0] / den; o0.y = acc[cn][1] / den;
            o0.z = acc[cn][2] / den; o0.w = acc[cn][3] / den;
            o1.x = acc[cn][4] / den; o1.y = acc[cn][5] / den;
            o1.z = acc[cn][6] / den; o1.w = acc[cn][7] / den;
            *(float4*)(OUT + base)     = o0;
            *(float4*)(OUT + base + 4) = o1;
        } else {
            float4 w0 = *(const float4*)(Wold + base);
            float4 w1 = *(const float4*)(Wold + base + 4);
            *(float4*)(OUT + base)     = w0;
            *(float4*)(OUT + base + 4) = w1;
        }
    }
}

// ============================================================
extern "C" void kernel_launch(void* const* d_in, const int* in_sizes, int n_in,
                              void* d_out, int out_size) {
    (void)in_sizes; (void)n_in; (void)out_size;
    const float* data    = (const float*)d_in[0];
    const float* weights = (const float*)d_in[1];
    const int*   itp     = (const int*)d_in[2];
    float*       out     = (float*)d_out;

    const int DIST_SMEM = (256 * 68 + 128 * 68) * 4;  // 104448 B
    cudaFuncSetAttribute(ker_dist, cudaFuncAttributeMaxDynamicSharedMemorySize,
                         DIST_SMEM);

    // 1) row squared-norms + schedule
    ker_sq<<<(MN + BSZ) / 8, 256>>>(weights, data, itp);
    // 2) fused distance GEMM + argmin (BMU)
    ker_dist<<<128, 256, DIST_SMEM>>>(data, weights);
    // 3) separable neighborhood factors
    ker_pxpy<<<BSZ, 128>>>();
    // 4) denom = PX^T PY
    ker_denom<<<128, 128>>>();
    // 5) numer GEMM + divide
    ker_numer<<<dim3(2, 128), 256>>>(data, weights, out);
}

// round 4
// speedup vs baseline: 1.4584x; 1.4584x over previous
#include <cuda_runtime.h>
#include <cuda_bf16.h>
#include <math.h>
#include <stdint.h>

#define BSZ   8192
#define MDIM  128
#define NDIM  128
#define KDIM  256
#define MN    16384

// -------- device scratch (no allocations allowed) --------
__device__ float g_wsq[MN];
__device__ float g_xsq[BSZ];
__device__ int   g_bmu[BSZ];
__device__ float g_pxT[MDIM * BSZ];    // [m][b]
__device__ float g_pyT[NDIM * BSZ];    // [n][b]
__device__ float g_sched[2];           // [0] = d = 2*sigma^2, [1] = lr
__device__ __nv_bfloat16 g_xthi[KDIM * BSZ];  // X^T hi  [d][b]
__device__ __nv_bfloat16 g_xtlo[KDIM * BSZ];  // X^T lo  [d][b]

// single shared dynamic-smem symbol for all kernels in this TU
extern __shared__ float sm[];

__device__ __forceinline__ uint32_t pk2(__nv_bfloat16 a, __nv_bfloat16 b) {
    __nv_bfloat162 t = __halves2bfloat162(a, b);
    return *reinterpret_cast<uint32_t*>(&t);
}

// m16n8k16 bf16 HMMA, fp32 accumulate (base-target PTX, no 'a' features)
__device__ __forceinline__ void mma_bf16(float* d,
                                         uint32_t a0, uint32_t a1,
                                         uint32_t a2, uint32_t a3,
                                         uint32_t b0, uint32_t b1) {
    asm volatile(
        "mma.sync.aligned.m16n8k16.row.col.f32.bf16.bf16.f32 "
        "{%0,%1,%2,%3}, {%4,%5,%6,%7}, {%8,%9}, {%0,%1,%2,%3};"
        : "+f"(d[0]), "+f"(d[1]), "+f"(d[2]), "+f"(d[3])
        : "r"(a0), "r"(a1), "r"(a2), "r"(a3), "r"(b0), "r"(b1));
}

// ============================================================
// Kernel 1: row sums of squares for W and X + scalar schedule.
// ============================================================
__global__ void ker_sq(const float* __restrict__ W,
                       const float* __restrict__ X,
                       const int*  __restrict__ itp) {
    if (blockIdx.x == 0 && threadIdx.x == 0) {
        int it = itp[0];
        double TAU   = 20.0 / log(64.0);
        double sigma = 64.0 * exp(-(double)it / TAU);
        g_sched[0] = (float)(2.0 * sigma * sigma);
        g_sched[1] = (float)(0.5 * exp(-(double)it / 20.0));
    }
    int warp = (blockIdx.x * blockDim.x + threadIdx.x) >> 5;
    int lane = threadIdx.x & 31;
    const float* src;
    float* dst;
    if (warp < MN) {
        src = W + (size_t)warp * KDIM; dst = g_wsq + warp;
    } else if (warp < MN + BSZ) {
        int row = warp - MN;
        src = X + (size_t)row * KDIM;  dst = g_xsq + row;
    } else return;
    float s = 0.f;
#pragma unroll
    for (int c = lane; c < KDIM; c += 32) { float v = src[c]; s += v * v; }
#pragma unroll
    for (int o = 16; o > 0; o >>= 1) s += __shfl_down_sync(0xffffffffu, s, o);
    if (lane == 0) *dst = s;
}

// ============================================================
// Kernel 1b: X [b][d] fp32 -> transposed split-bf16 XtHi/XtLo [d][b]
// ============================================================
__global__ void ker_prep(const float* __restrict__ X) {
    __shared__ float t[64][65];
    int bt = blockIdx.x;          // b tile (64)
    int dt = blockIdx.y;          // d tile (64)
    int tid = threadIdx.x;        // 256
#pragma unroll
    for (int s = 0; s < 16; s++) {
        int e = tid + 256 * s;
        int b = e >> 6, d = e & 63;
        t[b][d] = X[(size_t)(bt * 64 + b) * KDIM + dt * 64 + d];
    }
    __syncthreads();
#pragma unroll
    for (int s = 0; s < 8; s++) {
        int p = tid + 256 * s;
        int d = p >> 5, bp = p & 31;
        float a0 = t[bp * 2][d], a1 = t[bp * 2 + 1][d];
        __nv_bfloat16 h0 = __float2bfloat16_rn(a0);
        __nv_bfloat16 h1 = __float2bfloat16_rn(a1);
        __nv_bfloat16 l0 = __float2bfloat16_rn(a0 - __bfloat162float(h0));
        __nv_bfloat16 l1 = __float2bfloat16_rn(a1 - __bfloat162float(h1));
        size_t idx = (size_t)(dt * 64 + d) * BSZ + bt * 64 + bp * 2;
        *(uint32_t*)((char*)g_xthi + idx * 2) = pk2(h0, h1);
        *(uint32_t*)((char*)g_xtlo + idx * 2) = pk2(l0, l1);
    }
}

// ============================================================
// Kernel 2: fused distance GEMM + argmin (proven in R1).
// ============================================================
__global__ void __launch_bounds__(256, 1)
ker_dist(const float* __restrict__ X, const float* __restrict__ W) {
    float* Xs = sm;              // [256][68]
    float* Ws = sm + 256 * 68;   // [128][68]

    const int tid = threadIdx.x;
    const int tx  = tid & 15;
    const int ty  = tid >> 4;
    const int b0  = blockIdx.x * 64;

    for (int i = tid; i < 64 * 64; i += 256) {
        int b  = i & 63;
        int kq = i >> 6;
        float4 v = *(const float4*)(X + (size_t)(b0 + b) * KDIM + kq * 4);
        Xs[(kq * 4 + 0) * 68 + b] = v.x;
        Xs[(kq * 4 + 1) * 68 + b] = v.y;
        Xs[(kq * 4 + 2) * 68 + b] = v.z;
        Xs[(kq * 4 + 3) * 68 + b] = v.w;
    }

    float xsq[4];
#pragma unroll
    for (int r = 0; r < 4; r++) xsq[r] = g_xsq[b0 + tx * 4 + r];

    float bestv[4];
    int   bestj[4];
#pragma unroll
    for (int r = 0; r < 4; r++) { bestv[r] = 3.4e38f; bestj[r] = 0; }

    for (int jt = 0; jt < 128; ++jt) {
        const int j0 = jt * 128;
        float acc[4][8];
#pragma unroll
        for (int r = 0; r < 4; r++)
#pragma unroll
            for (int c = 0; c < 8; c++) acc[r][c] = 0.f;

        for (int kc = 0; kc < 4; ++kc) {
            __syncthreads();
            for (int i = tid; i < 128 * 16; i += 256) {
                int j  = i >> 4;
                int kq = i & 15;
                float4 v = *(const float4*)(W + (size_t)(j0 + j) * KDIM + kc * 64 + kq * 4);
                *(float4*)&Ws[j * 68 + kq * 4] = v;
            }
            __syncthreads();

#pragma unroll
            for (int k4 = 0; k4 < 64; k4 += 4) {
                const int kg = kc * 64 + k4;
                float4 xa = *(const float4*)&Xs[(kg + 0) * 68 + tx * 4];
                float4 xb = *(const float4*)&Xs[(kg + 1) * 68 + tx * 4];
                float4 xc = *(const float4*)&Xs[(kg + 2) * 68 + tx * 4];
                float4 xd = *(const float4*)&Xs[(kg + 3) * 68 + tx * 4];
#pragma unroll
                for (int c = 0; c < 8; c++) {
                    float4 wv = *(const float4*)&Ws[(ty * 8 + c) * 68 + k4];
                    acc[0][c] += xa.x * wv.x + xb.x * wv.y + xc.x * wv.z + xd.x * wv.w;
                    acc[1][c] += xa.y * wv.x + xb.y * wv.y + xc.y * wv.z + xd.y * wv.w;
                    acc[2][c] += xa.z * wv.x + xb.z * wv.y + xc.z * wv.z + xd.z * wv.w;
                    acc[3][c] += xa.w * wv.x + xb.w * wv.y + xc.w * wv.z + xd.w * wv.w;
                }
            }
        }

#pragma unroll
        for (int c = 0; c < 8; c++) {
            int j = j0 + ty * 8 + c;
            float w2 = g_wsq[j];
#pragma unroll
            for (int r = 0; r < 4; r++) {
                float s = sqrtf((xsq[r] + w2) - 2.0f * acc[r][c]);
                if (s < bestv[r]) { bestv[r] = s; bestj[r] = j; }
            }
        }
    }

    __syncthreads();
    float* sv = Ws;
    int*   si = (int*)(Ws + 64 * 16);
#pragma unroll
    for (int r = 0; r < 4; r++) {
        int b = tx * 4 + r;
        sv[b * 16 + ty] = bestv[r];
        si[b * 16 + ty] = bestj[r];
    }
    __syncthreads();
    if (tid < 64) {
        float bv = 3.4e38f;
        int   bj = MN;
        for (int t = 0; t < 16; t++) {
            float v = sv[tid * 16 + t];
            int  jj = si[tid * 16 + t];
            if (v < bv || (v == bv && jj < bj)) { bv = v; bj = jj; }
        }
        g_bmu[b0 + tid] = bj;
    }
}

// ============================================================
// Kernel 3: transposed neighborhood factors pxT[m][b], pyT[n][b]
// ============================================================
__global__ void ker_pxpy() {
    int i = blockIdx.x;           // 0..127 grid row/col index
    float d  = g_sched[0];
    float lr = g_sched[1];
    float fi = (float)i;
    for (int b = threadIdx.x; b < BSZ; b += 256) {
        int bmu = g_bmu[b];
        float dr = fi - (float)(bmu >> 7);
        float dc = fi - (float)(bmu & 127);
        g_pxT[(size_t)i * BSZ + b] = expf(-(dr * dr) / d);
        g_pyT[(size_t)i * BSZ + b] = lr * expf(-(dc * dc) / d);
    }
}

// ============================================================
// Kernel 4: numer via split-bf16 mma.sync HMMA (+fused denom).
// One CTA per m (128 CTAs, 256 thr = 8 warps in 2(n) x 4(d)).
// D[128 n x 256 d] = sum_b A[n][b] * X[b][d],  K=8192 in 64-chunks.
// A[n][b] = px[b,m]*py[b,n] built on the fly, split hi/lo bf16;
// X^T [d][b] pre-split hi/lo. 3 HMMA terms: hh + hl + lh.
// denom[n] accumulated in fp32 during A staging.
// SMEM rows padded to 160 B (64 bf16 data + 32 B) -> 2-way conflicts max.
// ============================================================
#define OFF_DSUM 0
#define OFF_AHI  512
#define OFF_ALO  (OFF_AHI + 128 * 160)      // 20992
#define OFF_XHI  (OFF_ALO + 128 * 160)      // 41472
#define OFF_XLO  (OFF_XHI + 256 * 160)      // 82432
#define NUMER_SMEM (OFF_XLO + 256 * 160)    // 123392

__global__ void __launch_bounds__(256, 1)
ker_numer_tc(const float* __restrict__ Wold, float* __restrict__ OUT) {
    char* base = (char*)sm;
    float* dsum = (float*)(base + OFF_DSUM);

    const int tid  = threadIdx.x;
    const int wid  = tid >> 5;
    const int lane = tid & 31;
    const int m    = blockIdx.x;

    const int n0 = (wid >> 2) * 64;   // warp n-origin (0 or 64)
    const int d0 = (wid & 3) * 64;    // warp d-origin (0,64,128,192)
    const int g  = lane >> 2;         // fragment row within 8
    const int c2 = (lane & 3) * 2;    // fragment col pair

    if (tid < 128) dsum[tid] = 0.f;

    float acc[4][8][4];
#pragma unroll
    for (int mt = 0; mt < 4; mt++)
#pragma unroll
        for (int nt = 0; nt < 8; nt++)
#pragma unroll
            for (int r = 0; r < 4; r++) acc[mt][nt][r] = 0.f;

    const float* pxm = g_pxT + (size_t)m * BSZ;
    const int bg = tid & 7;           // b-group (8 b) for A staging
    float dden[4] = {0.f, 0.f, 0.f, 0.f};

    for (int ch = 0; ch < 128; ch++) {
        const int b0c = ch * 64;
        __syncthreads();   // previous compute done before smem overwrite

        // ---- stage X^T tiles (hi & lo): 256 d-rows x 64 b ----
#pragma unroll
        for (int i = tid; i < 2048; i += 256) {
            int d = i >> 3, q = i & 7;
            size_t goff = ((size_t)d * BSZ + b0c + q * 8) * 2;
            *(float4*)(base + OFF_XHI + d * 160 + q * 16) =
                *(const float4*)((const char*)g_xthi + goff);
            *(float4*)(base + OFF_XLO + d * 160 + q * 16) =
                *(const float4*)((const char*)g_xtlo + goff);
        }

        // ---- stage A tiles (hi & lo): 128 n-rows x 64 b + denom ----
        float4 px0 = *(const float4*)(pxm + b0c + bg * 8);
        float4 px1 = *(const float4*)(pxm + b0c + bg * 8 + 4);
        float pxv[8] = {px0.x, px0.y, px0.z, px0.w, px1.x, px1.y, px1.z, px1.w};
#pragma unroll
        for (int s = 0; s < 4; s++) {
            int n = (tid >> 3) + 32 * s;
            const float* py = g_pyT + (size_t)n * BSZ + b0c + bg * 8;
            float4 p0 = *(const float4*)py;
            float4 p1 = *(const float4*)(py + 4);
            float a[8] = {pxv[0]*p0.x, pxv[1]*p0.y, pxv[2]*p0.z, pxv[3]*p0.w,
                          pxv[4]*p1.x, pxv[5]*p1.y, pxv[6]*p1.z, pxv[7]*p1.w};
            float ssum = 0.f;
            __nv_bfloat16 h[8], l[8];
#pragma unroll
            for (int j = 0; j < 8; j++) {
                ssum += a[j];
                h[j] = __float2bfloat16_rn(a[j]);
                l[j] = __float2bfloat16_rn(a[j] - __bfloat162float(h[j]));
            }
            dden[s] += ssum;
            uint4 hv = make_uint4(pk2(h[0],h[1]), pk2(h[2],h[3]),
                                  pk2(h[4],h[5]), pk2(h[6],h[7]));
            uint4 lv = make_uint4(pk2(l[0],l[1]), pk2(l[2],l[3]),
                                  pk2(l[4],l[5]), pk2(l[6],l[7]));
            *(uint4*)(base + OFF_AHI + n * 160 + bg * 16) = hv;
            *(uint4*)(base + OFF_ALO + n * 160 + bg * 16) = lv;
        }
        __syncthreads();

        // ---- compute: 4 k-steps of 16 ----
#pragma unroll
        for (int kk = 0; kk < 4; kk++) {
            const int kb = (kk * 16 + c2) * 2;   // byte col offset
            uint32_t ahi[4][4], alo[4][4];
#pragma unroll
            for (int mt = 0; mt < 4; mt++) {
                int roff = (n0 + mt * 16 + g) * 160 + kb;
                ahi[mt][0] = *(const uint32_t*)(base + OFF_AHI + roff);
                ahi[mt][1] = *(const uint32_t*)(base + OFF_AHI + roff + 8 * 160);
                ahi[mt][2] = *(const uint32_t*)(base + OFF_AHI + roff + 16);
                ahi[mt][3] = *(const uint32_t*)(base + OFF_AHI + roff + 8 * 160 + 16);
                alo[mt][0] = *(const uint32_t*)(base + OFF_ALO + roff);
                alo[mt][1] = *(const uint32_t*)(base + OFF_ALO + roff + 8 * 160);
                alo[mt][2] = *(const uint32_t*)(base + OFF_ALO + roff + 16);
                alo[mt][3] = *(const uint32_t*)(base + OFF_ALO + roff + 8 * 160 + 16);
            }
            uint32_t bhi[8][2], blo[8][2];
#pragma unroll
            for (int nt = 0; nt < 8; nt++) {
                int roff = (d0 + nt * 8 + g) * 160 + kb;
                bhi[nt][0] = *(const uint32_t*)(base + OFF_XHI + roff);
                bhi[nt][1] = *(const uint32_t*)(base + OFF_XHI + roff + 16);
                blo[nt][0] = *(const uint32_t*)(base + OFF_XLO + roff);
                blo[nt][1] = *(const uint32_t*)(base + OFF_XLO + roff + 16);
            }
#pragma unroll
            for (int mt = 0; mt < 4; mt++)
#pragma unroll
                for (int nt = 0; nt < 8; nt++) {
                    mma_bf16(acc[mt][nt], ahi[mt][0], ahi[mt][1], ahi[mt][2],
                             ahi[mt][3], bhi[nt][0], bhi[nt][1]);
                    mma_bf16(acc[mt][nt], ahi[mt][0], ahi[mt][1], ahi[mt][2],
                             ahi[mt][3], blo[nt][0], blo[nt][1]);
                    mma_bf16(acc[mt][nt], alo[mt][0], alo[mt][1], alo[mt][2],
                             alo[mt][3], bhi[nt][0], bhi[nt][1]);
                }
        }
    }

    // ---- denom reduction ----
    __syncthreads();
#pragma unroll
    for (int s = 0; s < 4; s++)
        atomicAdd(&dsum[(tid >> 3) + 32 * s], dden[s]);
    __syncthreads();

    // ---- epilogue: divide by denom, write ----
#pragma unroll
    for (int mt = 0; mt < 4; mt++) {
#pragma unroll
        for (int gg = 0; gg < 2; gg++) {
            int n = n0 + mt * 16 + g + gg * 8;
            float den = dsum[n];
            size_t rb = ((size_t)(m * 128 + n)) * KDIM;
#pragma unroll
            for (int nt = 0; nt < 8; nt++) {
                int dcol = d0 + nt * 8 + c2;
                float v0 = acc[mt][nt][gg * 2];
                float v1 = acc[mt][nt][gg * 2 + 1];
                float2 o;
                if (den != 0.f) {
                    o.x = v0 / den; o.y = v1 / den;
                } else {
                    o.x = Wold[rb + dcol]; o.y = Wold[rb + dcol + 1];
                }
                *(float2*)(OUT + rb + dcol) = o;
            }
        }
    }
}

// ============================================================
extern "C" void kernel_launch(void* const* d_in, const int* in_sizes, int n_in,
                              void* d_out, int out_size) {
    (void)in_sizes; (void)n_in; (void)out_size;
    const float* data    = (const float*)d_in[0];
    const float* weights = (const float*)d_in[1];
    const int*   itp     = (const int*)d_in[2];
    float*       out     = (float*)d_out;

    const int DIST_SMEM = (256 * 68 + 128 * 68) * 4;  // 104448 B
    cudaFuncSetAttribute(ker_dist, cudaFuncAttributeMaxDynamicSharedMemorySize,
                         DIST_SMEM);
    cudaFuncSetAttribute(ker_numer_tc, cudaFuncAttributeMaxDynamicSharedMemorySize,
                         NUMER_SMEM);

    // 1) row squared-norms + schedule
    ker_sq<<<(MN + BSZ) / 8, 256>>>(weights, data, itp);
    // 1b) X -> transposed split-bf16
    ker_prep<<<dim3(BSZ / 64, KDIM / 64), 256>>>(data);
    // 2) fused distance GEMM + argmin (BMU)
    ker_dist<<<128, 256, DIST_SMEM>>>(data, weights);
    // 3) transposed neighborhood factors
    ker_pxpy<<<128, 256>>>();
    // 4) numer HMMA GEMM (+fused denom) + divide
    ker_numer_tc<<<128, 256, NUMER_SMEM>>>(weights, out);
}

// round 5
// speedup vs baseline: 3.3304x; 2.2835x over previous
#include <cuda_runtime.h>
#include <cuda_bf16.h>
#include <cuda_fp16.h>
#include <math.h>
#include <stdint.h>
#include <float.h>

#define BSZ   8192
#define MDIM  128
#define NDIM  128
#define KDIM  256
#define MN    16384

// -------- device scratch (no allocations allowed) --------
__device__ float g_wsq[MN];
__device__ float g_pxT[MDIM * BSZ];    // [m][b]
__device__ float g_pyT[NDIM * BSZ];    // [n][b]
__device__ float g_sched[2];           // [0] = d = 2*sigma^2, [1] = lr
__device__ __nv_bfloat16 g_xthi[KDIM * BSZ];  // X^T hi (bf16) [d][b]  (numer)
__device__ __nv_bfloat16 g_xtlo[KDIM * BSZ];  // X^T lo (bf16) [d][b]  (numer)
__device__ __align__(16) __half g_whi[MN * KDIM];   // W hi (fp16) [j][k]
__device__ __align__(16) __half g_wlo[MN * KDIM];   // W lo
__device__ __align__(16) __half g_xhi[BSZ * KDIM];  // X hi (fp16) [b][k]
__device__ __align__(16) __half g_xlo[BSZ * KDIM];  // X lo
__device__ float g_pz[2 * BSZ];        // partial argmin value per (half, b)
__device__ int   g_pj[2 * BSZ];        // partial argmin index (global j)

// single shared dynamic-smem symbol for all kernels in this TU
extern __shared__ float sm[];

__device__ __forceinline__ uint32_t smem_u32(const void* p) {
    uint32_t a;
    asm("{ .reg .u64 t; cvta.to.shared.u64 t, %1; cvt.u32.u64 %0, t; }"
        : "=r"(a) : "l"(p));
    return a;
}
__device__ __forceinline__ uint32_t pk2(__nv_bfloat16 a, __nv_bfloat16 b) {
    __nv_bfloat162 t = __halves2bfloat162(a, b);
    return *reinterpret_cast<uint32_t*>(&t);
}

// m16n8k16 HMMA fp32 accumulate (base-target PTX)
__device__ __forceinline__ void mma_bf16(float* d,
                                         uint32_t a0, uint32_t a1,
                                         uint32_t a2, uint32_t a3,
                                         uint32_t b0, uint32_t b1) {
    asm volatile(
        "mma.sync.aligned.m16n8k16.row.col.f32.bf16.bf16.f32 "
        "{%0,%1,%2,%3}, {%4,%5,%6,%7}, {%8,%9}, {%0,%1,%2,%3};"
        : "+f"(d[0]), "+f"(d[1]), "+f"(d[2]), "+f"(d[3])
        : "r"(a0), "r"(a1), "r"(a2), "r"(a3), "r"(b0), "r"(b1));
}
__device__ __forceinline__ void mma_f16(float* d,
                                        uint32_t a0, uint32_t a1,
                                        uint32_t a2, uint32_t a3,
                                        uint32_t b0, uint32_t b1) {
    asm volatile(
        "mma.sync.aligned.m16n8k16.row.col.f32.f16.f16.f32 "
        "{%0,%1,%2,%3}, {%4,%5,%6,%7}, {%8,%9}, {%0,%1,%2,%3};"
        : "+f"(d[0]), "+f"(d[1]), "+f"(d[2]), "+f"(d[3])
        : "r"(a0), "r"(a1), "r"(a2), "r"(a3), "r"(b0), "r"(b1));
}

__device__ __forceinline__ void cpa16(uint32_t saddr, const void* g) {
    asm volatile("cp.async.cg.shared.global [%0], [%1], 16;"
                 :: "r"(saddr), "l"(g));
}
#define CPA_COMMIT() asm volatile("cp.async.commit_group;" ::: "memory")
#define CPA_WAIT1()  asm volatile("cp.async.wait_group 1;" ::: "memory")

// ============================================================
// Kernel 1: wsq (row sums of squares of W) + scalar schedule.
// ============================================================
__global__ void ker_sq(const float* __restrict__ W,
                       const int*  __restrict__ itp) {
    if (blockIdx.x == 0 && threadIdx.x == 0) {
        int it = itp[0];
        double TAU   = 20.0 / log(64.0);
        double sigma = 64.0 * exp(-(double)it / TAU);
        g_sched[0] = (float)(2.0 * sigma * sigma);
        g_sched[1] = (float)(0.5 * exp(-(double)it / 20.0));
    }
    int warp = (blockIdx.x * blockDim.x + threadIdx.x) >> 5;
    int lane = threadIdx.x & 31;
    if (warp >= MN) return;
    const float* src = W + (size_t)warp * KDIM;
    float s = 0.f;
#pragma unroll
    for (int c = lane; c < KDIM; c += 32) { float v = src[c]; s += v * v; }
#pragma unroll
    for (int o = 16; o > 0; o >>= 1) s += __shfl_down_sync(0xffffffffu, s, o);
    if (lane == 0) g_wsq[warp] = s;
}

// ============================================================
// Kernel 1b: fp16 hi/lo row-major splits of W and X (dist kernel inputs)
// Processes float2 pairs; W pairs first, then X pairs.
// ============================================================
#define WPAIRS (MN * KDIM / 2)
#define XPAIRS (BSZ * KDIM / 2)
__global__ void ker_split(const float* __restrict__ W,
                          const float* __restrict__ X) {
    int idx = blockIdx.x * 256 + threadIdx.x;
    const float* src;
    __half *dhi, *dlo;
    int p;
    if (idx < WPAIRS) {
        src = W; dhi = g_whi; dlo = g_wlo; p = idx;
    } else if (idx < WPAIRS + XPAIRS) {
        src = X; dhi = g_xhi; dlo = g_xlo; p = idx - WPAIRS;
    } else return;
    float2 v = *(const float2*)(src + (size_t)p * 2);
    __half h0 = __float2half_rn(v.x);
    __half h1 = __float2half_rn(v.y);
    __half l0 = __float2half_rn(v.x - __half2float(h0));
    __half l1 = __float2half_rn(v.y - __half2float(h1));
    *(__half2*)(dhi + (size_t)p * 2) = __halves2half2(h0, h1);
    *(__half2*)(dlo + (size_t)p * 2) = __halves2half2(l0, l1);
}

// ============================================================
// Kernel 1c: X [b][d] fp32 -> transposed split-bf16 (numer inputs)
// ============================================================
__global__ void ker_prep(const float* __restrict__ X) {
    __shared__ float t[64][65];
    int bt = blockIdx.x;          // b tile (64)
    int dt = blockIdx.y;          // d tile (64)
    int tid = threadIdx.x;        // 256
#pragma unroll
    for (int s = 0; s < 16; s++) {
        int e = tid + 256 * s;
        int b = e >> 6, d = e & 63;
        t[b][d] = X[(size_t)(bt * 64 + b) * KDIM + dt * 64 + d];
    }
    __syncthreads();
#pragma unroll
    for (int s = 0; s < 8; s++) {
        int p = tid + 256 * s;
        int d = p >> 5, bp = p & 31;
        float a0 = t[bp * 2][d], a1 = t[bp * 2 + 1][d];
        __nv_bfloat16 h0 = __float2bfloat16_rn(a0);
        __nv_bfloat16 h1 = __float2bfloat16_rn(a1);
        __nv_bfloat16 l0 = __float2bfloat16_rn(a0 - __bfloat162float(h0));
        __nv_bfloat16 l1 = __float2bfloat16_rn(a1 - __bfloat162float(h1));
        size_t idx = (size_t)(dt * 64 + d) * BSZ + bt * 64 + bp * 2;
        *(uint32_t*)((char*)g_xthi + idx * 2) = pk2(h0, h1);
        *(uint32_t*)((char*)g_xtlo + idx * 2) = pk2(l0, l1);
    }
}

// ============================================================
// Kernel 2: fused distance GEMM (split-fp16 HMMA) + argmin.
// grid (64 b-groups, 2 j-halves), 256 thr. CTA: 128 b x 8192 j.
// score z = wsq[j] - 2*dot (monotone equiv of ref's sqrt form).
// X tile [128b x 256k] hi/lo persistent; W streamed 128j x 64k
// hi/lo chunks, cp.async double-buffered. 3 MMA terms hh+hl+lh.
// ============================================================
#define XS_STRIDE 544                       // 256*2 + 32 pad
#define OFF_XHI2  0
#define OFF_XLO2  (128 * XS_STRIDE)         // 69632
#define OFF_WBUF  (2 * 128 * XS_STRIDE)     // 139264
#define WBUF_SZ   40960                     // per buffer: hi 128*160 + lo 128*160
#define WLO_OFF   20480
#define DIST_SMEM (OFF_WBUF + 2 * WBUF_SZ)  // 221184

__device__ __forceinline__ void dist_prefetch(uint32_t sbase, int ci,
                                              int half, int tid) {
    int jt = ci >> 2, kc = ci & 3;
    uint32_t dbuf = sbase + OFF_WBUF + (uint32_t)(ci & 1) * WBUF_SZ;
    size_t gro = ((size_t)(half * 8192 + jt * 128)) * KDIM + kc * 64;
#pragma unroll
    for (int t = 0; t < 4; t++) {
        int i = tid + 256 * t;          // 1024 16B segs per operand
        int r = i >> 3, s = i & 7;
        const char* sh = (const char*)(g_whi + gro + (size_t)r * KDIM) + s * 16;
        const char* sl = (const char*)(g_wlo + gro + (size_t)r * KDIM) + s * 16;
        cpa16(dbuf + r * 160 + s * 16, sh);
        cpa16(dbuf + WLO_OFF + r * 160 + s * 16, sl);
    }
}

__global__ void __launch_bounds__(256, 1)
ker_dist_mma() {
    char* base = (char*)sm;
    uint32_t sbase = smem_u32(base);
    const int tid  = threadIdx.x;
    const int lane = tid & 31;
    const int wid  = tid >> 5;
    const int wb   = wid >> 2;        // warp b-group (0..1) -> 64 b each
    const int wj   = wid & 3;         // warp j-group (0..3) -> 32 j each
    const int g    = lane >> 2;
    const int c2   = (lane & 3) * 2;
    const int b0   = blockIdx.x * 128;
    const int half = blockIdx.y;
    const int jbase = half * 8192;

    // ---- load X tile (hi/lo fp16), 128 rows x 512B ----
#pragma unroll
    for (int t = 0; t < 16; t++) {
        int i = tid + 256 * t;         // 4096 16B segs
        int r = i >> 5, s = i & 31;
        *(uint4*)(base + OFF_XHI2 + r * XS_STRIDE + s * 16) =
            *(const uint4*)((const char*)(g_xhi + (size_t)(b0 + r) * KDIM) + s * 16);
        *(uint4*)(base + OFF_XLO2 + r * XS_STRIDE + s * 16) =
            *(const uint4*)((const char*)(g_xlo + (size_t)(b0 + r) * KDIM) + s * 16);
    }

    float bz[8];
    int   bj[8];
#pragma unroll
    for (int i = 0; i < 8; i++) { bz[i] = FLT_MAX; bj[i] = 0; }

    dist_prefetch(sbase, 0, half, tid);
    CPA_COMMIT();

    float acc[4][4][4];

    for (int ci = 0; ci < 256; ci++) {
        const int jt = ci >> 2, kc = ci & 3;
        if (ci + 1 < 256) dist_prefetch(sbase, ci + 1, half, tid);
        CPA_COMMIT();
        CPA_WAIT1();
        __syncthreads();

        if (kc == 0) {
#pragma unroll
            for (int bt = 0; bt < 4; bt++)
#pragma unroll
                for (int nt = 0; nt < 4; nt++)
#pragma unroll
                    for (int r = 0; r < 4; r++) acc[bt][nt][r] = 0.f;
        }

        const uint32_t wboff = OFF_WBUF + (uint32_t)(ci & 1) * WBUF_SZ;
#pragma unroll
        for (int ks = 0; ks < 4; ks++) {
            const int kbX = (kc * 64 + ks * 16 + c2) * 2;
            uint32_t ahi[4][4], alo[4][4];
#pragma unroll
            for (int bt = 0; bt < 4; bt++) {
                int ro = (wb * 64 + bt * 16 + g) * XS_STRIDE + kbX;
                ahi[bt][0] = *(const uint32_t*)(base + OFF_XHI2 + ro);
                ahi[bt][1] = *(const uint32_t*)(base + OFF_XHI2 + ro + 8 * XS_STRIDE);
                ahi[bt][2] = *(const uint32_t*)(base + OFF_XHI2 + ro + 16);
                ahi[bt][3] = *(const uint32_t*)(base + OFF_XHI2 + ro + 8 * XS_STRIDE + 16);
                alo[bt][0] = *(const uint32_t*)(base + OFF_XLO2 + ro);
                alo[bt][1] = *(const uint32_t*)(base + OFF_XLO2 + ro + 8 * XS_STRIDE);
                alo[bt][2] = *(const uint32_t*)(base + OFF_XLO2 + ro + 16);
                alo[bt][3] = *(const uint32_t*)(base + OFF_XLO2 + ro + 8 * XS_STRIDE + 16);
            }
            const int kbW = (ks * 16 + c2) * 2;
            uint32_t bh[4][2], bl[4][2];
#pragma unroll
            for (int nt = 0; nt < 4; nt++) {
                int ro = (wj * 32 + nt * 8 + g) * 160 + kbW;
                bh[nt][0] = *(const uint32_t*)(base + wboff + ro);
                bh[nt][1] = *(const uint32_t*)(base + wboff + ro + 16);
                bl[nt][0] = *(const uint32_t*)(base + wboff + WLO_OFF + ro);
                bl[nt][1] = *(const uint32_t*)(base + wboff + WLO_OFF + ro + 16);
            }
#pragma unroll
            for (int bt = 0; bt < 4; bt++)
#pragma unroll
                for (int nt = 0; nt < 4; nt++) {
                    mma_f16(acc[bt][nt], ahi[bt][0], ahi[bt][1], ahi[bt][2],
                            ahi[bt][3], bh[nt][0], bh[nt][1]);
                    mma_f16(acc[bt][nt], ahi[bt][0], ahi[bt][1], ahi[bt][2],
                            ahi[bt][3], bl[nt][0], bl[nt][1]);
                    mma_f16(acc[bt][nt], alo[bt][0], alo[bt][1], alo[bt][2],
                            alo[bt][3], bh[nt][0], bh[nt][1]);
                }
        }

        if (kc == 3) {
            const int j0 = jt * 128 + wj * 32;
#pragma unroll
            for (int nt = 0; nt < 4; nt++) {
                int jg = j0 + nt * 8 + c2;          // local j of column c2
                float w0 = g_wsq[jbase + jg];
                float w1 = g_wsq[jbase + jg + 1];
#pragma unroll
                for (int bt = 0; bt < 4; bt++) {
                    float z00 = fmaf(-2.f, acc[bt][nt][0], w0);
                    float z01 = fmaf(-2.f, acc[bt][nt][1], w1);
                    float z10 = fmaf(-2.f, acc[bt][nt][2], w0);
                    float z11 = fmaf(-2.f, acc[bt][nt][3], w1);
                    int s0 = bt * 2, s1 = bt * 2 + 1;
                    if (z00 < bz[s0]) { bz[s0] = z00; bj[s0] = jg; }
                    if (z01 < bz[s0]) { bz[s0] = z01; bj[s0] = jg + 1; }
                    if (z10 < bz[s1]) { bz[s1] = z10; bj[s1] = jg; }
                    if (z11 < bz[s1]) { bz[s1] = z11; bj[s1] = jg + 1; }
                }
            }
        }
        __syncthreads();
    }

    // ---- cross-lane (c bits) argmin reduction ----
#pragma unroll
    for (int i = 0; i < 8; i++) {
        float z = bz[i]; int j = bj[i];
#pragma unroll
        for (int off = 1; off <= 2; off <<= 1) {
            float oz = __shfl_xor_sync(0xffffffffu, z, off);
            int   oj = __shfl_xor_sync(0xffffffffu, j, off);
            if (oz < z || (oz == z && oj < j)) { z = oz; j = oj; }
        }
        bz[i] = z; bj[i] = j;
    }

    // ---- cross-warp reduction via smem (reuse W buffers) ----
    float* sz = (float*)(base + OFF_WBUF);
    int*   sj = (int*)(base + OFF_WBUF + 2048);
    if ((lane & 3) == 0) {
#pragma unroll
        for (int i = 0; i < 8; i++) {
            int bt = i >> 1, h = i & 1;
            int row = wb * 64 + bt * 16 + g + 8 * h;
            sz[row * 4 + wj] = bz[i];
            sj[row * 4 + wj] = bj[i];
        }
    }
    __syncthreads();
    if (tid < 128) {
        float z = sz[tid * 4]; int j = sj[tid * 4];
#pragma unroll
        for (int t = 1; t < 4; t++) {
            float oz = sz[tid * 4 + t]; int oj = sj[tid * 4 + t];
            if (oz < z || (oz == z && oj < j)) { z = oz; j = oj; }
        }
        g_pz[half * BSZ + b0 + tid] = z;
        g_pj[half * BSZ + b0 + tid] = jbase + j;
    }
}

// ============================================================
// Kernel 3: combine halves -> BMU, then transposed neighborhood
// factors pxT[m][b], pyT[n][b].
// ============================================================
__global__ void ker_pxpy() {
    int i = blockIdx.x;           // 0..127 grid row/col index
    float d  = g_sched[0];
    float lr = g_sched[1];
    float fi = (float)i;
    for (int b = threadIdx.x; b < BSZ; b += 256) {
        float z0 = g_pz[b], z1 = g_pz[BSZ + b];
        int bmu = (z1 < z0) ? g_pj[BSZ + b] : g_pj[b];  // tie -> half0 (lower j)
        float dr = fi - (float)(bmu >> 7);
        float dc = fi - (float)(bmu & 127);
        g_pxT[(size_t)i * BSZ + b] = expf(-(dr * dr) / d);
        g_pyT[(size_t)i * BSZ + b] = lr * expf(-(dc * dc) / d);
    }
}

// ============================================================
// Kernel 4: numer via split-bf16 mma.sync HMMA (+fused denom).
// (unchanged from R4 — proven)
// ============================================================
#define OFF_DSUM 0
#define OFF_AHI  512
#define OFF_ALO  (OFF_AHI + 128 * 160)
#define OFF_XHI  (OFF_ALO + 128 * 160)
#define OFF_XLO  (OFF_XHI + 256 * 160)
#define NUMER_SMEM (OFF_XLO + 256 * 160)

__global__ void __launch_bounds__(256, 1)
ker_numer_tc(const float* __restrict__ Wold, float* __restrict__ OUT) {
    char* base = (char*)sm;
    float* dsum = (float*)(base + OFF_DSUM);

    const int tid  = threadIdx.x;
    const int wid  = tid >> 5;
    const int lane = tid & 31;
    const int m    = blockIdx.x;

    const int n0 = (wid >> 2) * 64;
    const int d0 = (wid & 3) * 64;
    const int g  = lane >> 2;
    const int c2 = (lane & 3) * 2;

    if (tid < 128) dsum[tid] = 0.f;

    float acc[4][8][4];
#pragma unroll
    for (int mt = 0; mt < 4; mt++)
#pragma unroll
        for (int nt = 0; nt < 8; nt++)
#pragma unroll
            for (int r = 0; r < 4; r++) acc[mt][nt][r] = 0.f;

    const float* pxm = g_pxT + (size_t)m * BSZ;
    const int bg = tid & 7;
    float dden[4] = {0.f, 0.f, 0.f, 0.f};

    for (int ch = 0; ch < 128; ch++) {
        const int b0c = ch * 64;
        __syncthreads();

#pragma unroll
        for (int i = tid; i < 2048; i += 256) {
            int d = i >> 3, q = i & 7;
            size_t goff = ((size_t)d * BSZ + b0c + q * 8) * 2;
            *(float4*)(base + OFF_XHI + d * 160 + q * 16) =
                *(const float4*)((const char*)g_xthi + goff);
            *(float4*)(base + OFF_XLO + d * 160 + q * 16) =
                *(const float4*)((const char*)g_xtlo + goff);
        }

        float4 px0 = *(const float4*)(pxm + b0c + bg * 8);
        float4 px1 = *(const float4*)(pxm + b0c + bg * 8 + 4);
        float pxv[8] = {px0.x, px0.y, px0.z, px0.w, px1.x, px1.y, px1.z, px1.w};
#pragma unroll
        for (int s = 0; s < 4; s++) {
            int n = (tid >> 3) + 32 * s;
            const float* py = g_pyT + (size_t)n * BSZ + b0c + bg * 8;
            float4 p0 = *(const float4*)py;
            float4 p1 = *(const float4*)(py + 4);
            float a[8] = {pxv[0]*p0.x, pxv[1]*p0.y, pxv[2]*p0.z, pxv[3]*p0.w,
                          pxv[4]*p1.x, pxv[5]*p1.y, pxv[6]*p1.z, pxv[7]*p1.w};
            float ssum = 0.f;
            __nv_bfloat16 h[8], l[8];
#pragma unroll
            for (int j = 0; j < 8; j++) {
                ssum += a[j];
                h[j] = __float2bfloat16_rn(a[j]);
                l[j] = __float2bfloat16_rn(a[j] - __bfloat162float(h[j]));
            }
            dden[s] += ssum;
            uint4 hv = make_uint4(pk2(h[0],h[1]), pk2(h[2],h[3]),
                                  pk2(h[4],h[5]), pk2(h[6],h[7]));
            uint4 lv = make_uint4(pk2(l[0],l[1]), pk2(l[2],l[3]),
                                  pk2(l[4],l[5]), pk2(l[6],l[7]));
            *(uint4*)(base + OFF_AHI + n * 160 + bg * 16) = hv;
            *(uint4*)(base + OFF_ALO + n * 160 + bg * 16) = lv;
        }
        __syncthreads();

#pragma unroll
        for (int kk = 0; kk < 4; kk++) {
            const int kb = (kk * 16 + c2) * 2;
            uint32_t ahi[4][4], alo[4][4];
#pragma unroll
            for (int mt = 0; mt < 4; mt++) {
                int roff = (n0 + mt * 16 + g) * 160 + kb;
                ahi[mt][0] = *(const uint32_t*)(base + OFF_AHI + roff);
                ahi[mt][1] = *(const uint32_t*)(base + OFF_AHI + roff + 8 * 160);
                ahi[mt][2] = *(const uint32_t*)(base + OFF_AHI + roff + 16);
                ahi[mt][3] = *(const uint32_t*)(base + OFF_AHI + roff + 8 * 160 + 16);
                alo[mt][0] = *(const uint32_t*)(base + OFF_ALO + roff);
                alo[mt][1] = *(const uint32_t*)(base + OFF_ALO + roff + 8 * 160);
                alo[mt][2] = *(const uint32_t*)(base + OFF_ALO + roff + 16);
                alo[mt][3] = *(const uint32_t*)(base + OFF_ALO + roff + 8 * 160 + 16);
            }
            uint32_t bhi[8][2], blo[8][2];
#pragma unroll
            for (int nt = 0; nt < 8; nt++) {
                int roff = (d0 + nt * 8 + g) * 160 + kb;
                bhi[nt][0] = *(const uint32_t*)(base + OFF_XHI + roff);
                bhi[nt][1] = *(const uint32_t*)(base + OFF_XHI + roff + 16);
                blo[nt][0] = *(const uint32_t*)(base + OFF_XLO + roff);
                blo[nt][1] = *(const uint32_t*)(base + OFF_XLO + roff + 16);
            }
#pragma unroll
            for (int mt = 0; mt < 4; mt++)
#pragma unroll
                for (int nt = 0; nt < 8; nt++) {
                    mma_bf16(acc[mt][nt], ahi[mt][0], ahi[mt][1], ahi[mt][2],
                             ahi[mt][3], bhi[nt][0], bhi[nt][1]);
                    mma_bf16(acc[mt][nt], ahi[mt][0], ahi[mt][1], ahi[mt][2],
                             ahi[mt][3], blo[nt][0], blo[nt][1]);
                    mma_bf16(acc[mt][nt], alo[mt][0], alo[mt][1], alo[mt][2],
                             alo[mt][3], bhi[nt][0], bhi[nt][1]);
                }
        }
    }

    __syncthreads();
#pragma unroll
    for (int s = 0; s < 4; s++)
        atomicAdd(&dsum[(tid >> 3) + 32 * s], dden[s]);
    __syncthreads();

#pragma unroll
    for (int mt = 0; mt < 4; mt++) {
#pragma unroll
        for (int gg = 0; gg < 2; gg++) {
            int n = n0 + mt * 16 + g + gg * 8;
            float den = dsum[n];
            size_t rb = ((size_t)(m * 128 + n)) * KDIM;
#pragma unroll
            for (int nt = 0; nt < 8; nt++) {
                int dcol = d0 + nt * 8 + c2;
                float v0 = acc[mt][nt][gg * 2];
                float v1 = acc[mt][nt][gg * 2 + 1];
                float2 o;
                if (den != 0.f) {
                    o.x = v0 / den; o.y = v1 / den;
                } else {
                    o.x = Wold[rb + dcol]; o.y = Wold[rb + dcol + 1];
                }
                *(float2*)(OUT + rb + dcol) = o;
            }
        }
    }
}

// ============================================================
extern "C" void kernel_launch(void* const* d_in, const int* in_sizes, int n_in,
                              void* d_out, int out_size) {
    (void)in_sizes; (void)n_in; (void)out_size;
    const float* data    = (const float*)d_in[0];
    const float* weights = (const float*)d_in[1];
    const int*   itp     = (const int*)d_in[2];
    float*       out     = (float*)d_out;

    cudaFuncSetAttribute(ker_dist_mma, cudaFuncAttributeMaxDynamicSharedMemorySize,
                         DIST_SMEM);
    cudaFuncSetAttribute(ker_numer_tc, cudaFuncAttributeMaxDynamicSharedMemorySize,
                         NUMER_SMEM);

    // 1) W row squared-norms + schedule
    ker_sq<<<MN / 8, 256>>>(weights, itp);
    // 1b) fp16 hi/lo splits of W and X (dist)
    ker_split<<<(WPAIRS + XPAIRS) / 256, 256>>>(weights, data);
    // 1c) X -> transposed split-bf16 (numer)
    ker_prep<<<dim3(BSZ / 64, KDIM / 64), 256>>>(data);
    // 2) fused distance HMMA GEMM + argmin (partial per j-half)
    ker_dist_mma<<<dim3(64, 2), 256, DIST_SMEM>>>();
    // 3) combine halves -> BMU -> neighborhood factors
    ker_pxpy<<<128, 256>>>();
    // 4) numer HMMA GEMM (+fused denom) + divide
    ker_numer_tc<<<128, 256, NUMER_SMEM>>>(weights, out);
}